// round 1
// baseline (speedup 1.0000x reference)
#include <cuda_runtime.h>
#include <cstdint>
#include <cstddef>

#define BB 64
#define TT 2048
#define DD 256
#define HH 512
#define GCN 2048   /* 4*HH gate columns: [j|i|f|o] */
#define RBLOCKS 128

// ---------------- scratch (device globals: allocation-free rule) ----------------
__device__ float g_xproj[(size_t)TT * GCN * BB];   // [t][gc][b]  (1 GiB)
__device__ float g_hs[(size_t)TT * BB * HH];       // [t][b][h]   (256 MiB)
__device__ unsigned g_bar_gen;                     // grid barrier generation
__device__ unsigned g_bar_cnt;                     // grid barrier arrival count

__device__ __forceinline__ float fsigmoid_(float x) {
    return 1.0f / (1.0f + __expf(-x));
}
__device__ __forceinline__ float ftanh_(float x) {
    // overflow-safe tanh: e->inf => 1, e->0 => -1
    float e = __expf(2.0f * x);
    return 1.0f - 2.0f / (e + 1.0f);
}

// =====================================================================
// Kernel 1: input projections  xproj[t][gc][b] = bias[gc] + sum_d x[b][t][d]*W_g[d][hq]
// grid (16 gc-tiles of 128, 2048 t), 256 threads
// =====================================================================
__global__ void __launch_bounds__(256) proj_kernel(
    const float* __restrict__ x,
    const float* __restrict__ Wj, const float* __restrict__ Wi,
    const float* __restrict__ Wf, const float* __restrict__ Wo,
    const float* __restrict__ bj, const float* __restrict__ bi,
    const float* __restrict__ bf, const float* __restrict__ bo)
{
    extern __shared__ float sm[];
    float* Wsm = sm;                 // [256][128]
    float* Xsm = sm + 256 * 128;     // [64][260]  (pad 260 kills bank conflicts)

    const int t   = blockIdx.y;
    const int gc0 = blockIdx.x * 128;
    const int g   = gc0 >> 9;        // gate id 0..3
    const int hq0 = gc0 & 511;
    const float* W  = (g == 0) ? Wj : (g == 1) ? Wi : (g == 2) ? Wf : Wo;
    const float* bv = (g == 0) ? bj : (g == 1) ? bi : (g == 2) ? bf : bo;
    const int tid = threadIdx.x;

    // load W tile [256 d][128 c] (float4)
    for (int idx = tid; idx < 256 * 32; idx += 256) {
        int d = idx >> 5, c4 = idx & 31;
        *(float4*)(Wsm + d * 128 + c4 * 4) =
            *(const float4*)(W + (size_t)d * HH + hq0 + c4 * 4);
    }
    // load x tile [64 b][256 d] (float4), padded rows of 260
    for (int idx = tid; idx < 64 * 64; idx += 256) {
        int b = idx >> 6, d4 = idx & 63;
        *(float4*)(Xsm + b * 260 + d4 * 4) =
            *(const float4*)(x + ((size_t)b * TT + t) * DD + d4 * 4);
    }
    __syncthreads();

    const int tb = tid >> 4;   // 0..15 -> 4 batches each
    const int tc = tid & 15;   // 0..15 -> 8 cols (stride 16) each

    float acc[4][8];
#pragma unroll
    for (int j = 0; j < 4; j++)
#pragma unroll
        for (int i = 0; i < 8; i++) acc[j][i] = 0.0f;

#pragma unroll 4
    for (int d = 0; d < 256; d++) {
        float wv[8], xv[4];
#pragma unroll
        for (int i = 0; i < 8; i++) wv[i] = Wsm[d * 128 + tc + 16 * i];
#pragma unroll
        for (int j = 0; j < 4; j++) xv[j] = Xsm[(tb * 4 + j) * 260 + d];
#pragma unroll
        for (int j = 0; j < 4; j++)
#pragma unroll
            for (int i = 0; i < 8; i++)
                acc[j][i] = fmaf(xv[j], wv[i], acc[j][i]);
    }

#pragma unroll
    for (int i = 0; i < 8; i++) {
        int c = tc + 16 * i;
        float bb = bv[hq0 + c];
        float4 v = make_float4(acc[0][i] + bb, acc[1][i] + bb,
                               acc[2][i] + bb, acc[3][i] + bb);
        *(float4*)(g_xproj + ((size_t)t * GCN + gc0 + c) * BB + tb * 4) = v;
    }
}

// =====================================================================
// Kernel 2: persistent recurrence. 128 blocks x 256 threads.
// Block bk owns hq in [bk*4, bk*4+4) for all 4 gates (16 gate-columns).
// Warp (bh,g): 32 batches (bh half) x 4 hq for gate g; each lane owns a
// FULL 512-long dot product (no cross-lane reduction).
// =====================================================================
__global__ void __launch_bounds__(256) recur_kernel(
    const float* __restrict__ h0in, const float* __restrict__ c0in,
    const float* __restrict__ Uj, const float* __restrict__ Ui,
    const float* __restrict__ Uf, const float* __restrict__ Uo,
    float* __restrict__ dout)
{
    extern __shared__ float sm[];
    float* h_smf = sm;                       // [64][512] floats, xor-swizzled float4
    float* U_sm  = sm + 64 * 512;            // [512 hk][16 gc_local]
    float* gsm   = U_sm + 512 * 16;          // [16 gc_local][64 b]
    float* c_sm  = gsm + 16 * 64;            // [4 hql][64 b]

    const int tid = threadIdx.x;
    const int hq_base = blockIdx.x * 4;

    // load U slice: U_sm[hk][g*4+l] = U_g[hk][hq_base+l]   (one-time)
    {
        const float* Us0 = Uj; const float* Us1 = Ui;
        const float* Us2 = Uf; const float* Us3 = Uo;
        for (int idx = tid; idx < 512 * 16; idx += 256) {
            int hk = idx >> 4, L = idx & 15;
            int g = L >> 2, l = L & 3;
            const float* Up = (g == 0) ? Us0 : (g == 1) ? Us1 : (g == 2) ? Us2 : Us3;
            U_sm[idx] = Up[(size_t)hk * HH + hq_base + l];
        }
    }
    // init c slice
    {
        int l = tid & 3, b = tid >> 2;
        c_sm[l * 64 + b] = c0in[(size_t)b * HH + hq_base + l];
    }
    __syncthreads();

    const int wid  = tid >> 5;
    const int lane = tid & 31;
    const int bh   = wid & 1;        // batch half
    const int g    = wid >> 1;       // gate 0..3
    const int b    = bh * 32 + lane; // batch 0..63
    const int xm   = b & 7;          // xor swizzle mask (float4 units)

    float4* h4 = (float4*)h_smf;
    const float4* U4 = (const float4*)U_sm;   // U4[hk*4 + g] = 4 hql values

    for (int t = 0; t < TT; t++) {
        // ---- stage h_{t-1} into swizzled smem ----
        const float4* src = (t == 0) ? (const float4*)h0in
                                     : (const float4*)(g_hs + (size_t)(t - 1) * BB * HH);
        for (int idx = tid; idx < 64 * 128; idx += 256) {
            int bb = idx >> 7, k4 = idx & 127;
            h4[bb * 128 + (k4 ^ (bb & 7))] = src[idx];
        }
        __syncthreads();

        // ---- prefetch xproj for this warp's 4 outputs (hides DRAM latency) ----
        const float* xp = g_xproj + ((size_t)t * GCN + ((size_t)g * HH + hq_base)) * BB;
        float x0 = xp[0 * BB + b];
        float x1 = xp[1 * BB + b];
        float x2 = xp[2 * BB + b];
        float x3 = xp[3 * BB + b];

        // ---- dot products: acc_l = sum_hk h[b][hk] * U_g[hk][hq_base+l] ----
        float a0 = 0.f, a1 = 0.f, a2 = 0.f, a3 = 0.f;
#pragma unroll 4
        for (int k4 = 0; k4 < 128; k4++) {
            float4 hv = h4[b * 128 + (k4 ^ xm)];
            int hk = k4 << 2;
            float4 u0 = U4[(hk + 0) * 4 + g];
            float4 u1 = U4[(hk + 1) * 4 + g];
            float4 u2 = U4[(hk + 2) * 4 + g];
            float4 u3 = U4[(hk + 3) * 4 + g];
            a0 = fmaf(hv.x, u0.x, a0); a1 = fmaf(hv.x, u0.y, a1);
            a2 = fmaf(hv.x, u0.z, a2); a3 = fmaf(hv.x, u0.w, a3);
            a0 = fmaf(hv.y, u1.x, a0); a1 = fmaf(hv.y, u1.y, a1);
            a2 = fmaf(hv.y, u1.z, a2); a3 = fmaf(hv.y, u1.w, a3);
            a0 = fmaf(hv.z, u2.x, a0); a1 = fmaf(hv.z, u2.y, a1);
            a2 = fmaf(hv.z, u2.z, a2); a3 = fmaf(hv.z, u2.w, a3);
            a0 = fmaf(hv.w, u3.x, a0); a1 = fmaf(hv.w, u3.y, a1);
            a2 = fmaf(hv.w, u3.z, a2); a3 = fmaf(hv.w, u3.w, a3);
        }
        a0 += x0; a1 += x1; a2 += x2; a3 += x3;

        if (g == 2) {  // f gate: tanh (module default quirk)
            a0 = ftanh_(a0); a1 = ftanh_(a1); a2 = ftanh_(a2); a3 = ftanh_(a3);
        } else {       // j, i, o: sigmoid
            a0 = fsigmoid_(a0); a1 = fsigmoid_(a1);
            a2 = fsigmoid_(a2); a3 = fsigmoid_(a3);
        }
        gsm[(g * 4 + 0) * 64 + b] = a0;
        gsm[(g * 4 + 1) * 64 + b] = a1;
        gsm[(g * 4 + 2) * 64 + b] = a2;
        gsm[(g * 4 + 3) * 64 + b] = a3;
        __syncthreads();

        // ---- c/h update, write h_t (thread (l=hql, bb=batch)) ----
        {
            int l = tid & 3, bb = tid >> 2;
            float jv = gsm[(0 + l) * 64 + bb];
            float iv = gsm[(4 + l) * 64 + bb];
            float fv = gsm[(8 + l) * 64 + bb];
            float ov = gsm[(12 + l) * 64 + bb];
            float cv = fmaf(fv, c_sm[l * 64 + bb], iv * jv);
            c_sm[l * 64 + bb] = cv;
            float hv = ov * ftanh_(cv);
            g_hs[((size_t)t * BB + bb) * HH + hq_base + l] = hv;
        }

        // ---- grid barrier (all 128 blocks co-resident: 1 block/SM by smem) ----
        __syncthreads();
        if (tid == 0) {
            __threadfence();
            unsigned myg = *(volatile unsigned*)&g_bar_gen;
            if (atomicAdd(&g_bar_cnt, 1u) == RBLOCKS - 1) {
                g_bar_cnt = 0;
                __threadfence();
                *(volatile unsigned*)&g_bar_gen = myg + 1u;
            } else {
                while (*(volatile unsigned*)&g_bar_gen == myg) { __nanosleep(64); }
            }
            __threadfence();
        }
        __syncthreads();
    }

    // ---- epilogue: h_last, c_last ----
    {
        int l = tid & 3, bb = tid >> 2;
        size_t OH = (size_t)BB * TT * DD;
        float hlast = g_hs[((size_t)(TT - 1) * BB + bb) * HH + hq_base + l];
        dout[OH + (size_t)bb * HH + hq_base + l] = hlast;
        dout[OH + (size_t)BB * HH + (size_t)bb * HH + hq_base + l] = c_sm[l * 64 + bb];
    }
}

// =====================================================================
// Kernel 3: y[b][t][d] = sum_h hs[t][b][h] * Wy[h][d] + by[d]
// grid 2048 (t), 256 threads, K chunked by 128
// =====================================================================
__global__ void __launch_bounds__(256) ygemm_kernel(
    const float* __restrict__ Wy, const float* __restrict__ by,
    float* __restrict__ y)
{
    extern __shared__ float sm[];
    float* Wsm = sm;               // [128][256]
    float* Hsm = sm + 128 * 256;   // [64][132]

    const int t = blockIdx.x;
    const int tid = threadIdx.x;
    const int tb = tid >> 4, td = tid & 15;

    float acc[4][16];
#pragma unroll
    for (int j = 0; j < 4; j++)
#pragma unroll
        for (int i = 0; i < 16; i++) acc[j][i] = 0.0f;

    for (int kc = 0; kc < 4; kc++) {
        int h0 = kc * 128;
        __syncthreads();
        for (int idx = tid; idx < 128 * 64; idx += 256) {
            int r = idx >> 6, c4 = idx & 63;
            *(float4*)(Wsm + r * 256 + c4 * 4) =
                *(const float4*)(Wy + (size_t)(h0 + r) * DD + c4 * 4);
        }
        for (int idx = tid; idx < 64 * 32; idx += 256) {
            int bb = idx >> 5, k4 = idx & 31;
            *(float4*)(Hsm + bb * 132 + k4 * 4) =
                *(const float4*)(g_hs + ((size_t)t * BB + bb) * HH + h0 + k4 * 4);
        }
        __syncthreads();

#pragma unroll 2
        for (int k = 0; k < 128; k++) {
            float wv[16], xv[4];
#pragma unroll
            for (int i = 0; i < 16; i++) wv[i] = Wsm[k * 256 + td + 16 * i];
#pragma unroll
            for (int j = 0; j < 4; j++) xv[j] = Hsm[(tb * 4 + j) * 132 + k];
#pragma unroll
            for (int j = 0; j < 4; j++)
#pragma unroll
                for (int i = 0; i < 16; i++)
                    acc[j][i] = fmaf(xv[j], wv[i], acc[j][i]);
        }
    }

#pragma unroll
    for (int i = 0; i < 16; i++) {
        int d = td + 16 * i;
        float bb = by[d];
#pragma unroll
        for (int j = 0; j < 4; j++) {
            y[(((size_t)(tb * 4 + j)) * TT + t) * DD + d] = acc[j][i] + bb;
        }
    }
}

// =====================================================================
extern "C" void kernel_launch(void* const* d_in, const int* in_sizes, int n_in,
                              void* d_out, int out_size)
{
    (void)in_sizes; (void)n_in; (void)out_size;
    const float* x  = (const float*)d_in[0];
    const float* h0 = (const float*)d_in[1];
    const float* c0 = (const float*)d_in[2];
    const float* Wj = (const float*)d_in[3];
    const float* Wi = (const float*)d_in[4];
    const float* Wf = (const float*)d_in[5];
    const float* Wo = (const float*)d_in[6];
    const float* Uj = (const float*)d_in[7];
    const float* Ui = (const float*)d_in[8];
    const float* Uf = (const float*)d_in[9];
    const float* Uo = (const float*)d_in[10];
    const float* bj = (const float*)d_in[11];
    const float* bi = (const float*)d_in[12];
    const float* bf = (const float*)d_in[13];
    const float* bo = (const float*)d_in[14];
    const float* Wy = (const float*)d_in[15];
    const float* by = (const float*)d_in[16];
    float* out = (float*)d_out;

    const size_t smem_proj = (size_t)(256 * 128 + 64 * 260) * 4;            // 197,632
    const size_t smem_rec  = (size_t)(64 * 512 + 512 * 16 + 16 * 64 + 4 * 64) * 4; // 168,960
    const size_t smem_y    = (size_t)(128 * 256 + 64 * 132) * 4;            // 164,864

    cudaFuncSetAttribute(proj_kernel,  cudaFuncAttributeMaxDynamicSharedMemorySize, (int)smem_proj);
    cudaFuncSetAttribute(recur_kernel, cudaFuncAttributeMaxDynamicSharedMemorySize, (int)smem_rec);
    cudaFuncSetAttribute(ygemm_kernel, cudaFuncAttributeMaxDynamicSharedMemorySize, (int)smem_y);

    proj_kernel<<<dim3(16, TT), 256, smem_proj>>>(x, Wj, Wi, Wf, Wo, bj, bi, bf, bo);
    recur_kernel<<<RBLOCKS, 256, smem_rec>>>(h0, c0, Uj, Ui, Uf, Uo, out);
    ygemm_kernel<<<TT, 256, smem_y>>>(Wy, by, out);
}